// round 2
// baseline (speedup 1.0000x reference)
#include <cuda_runtime.h>
#include <cstddef>

#define B_ 4
#define T_ 4096
#define C_ 512
#define CHUNK 64
#define NCHUNK (T_/CHUNK)

typedef unsigned long long ull_t;

__device__ __forceinline__ float2 ffma2(float2 a, float2 b, float2 c) {
    ull_t ua = *reinterpret_cast<ull_t*>(&a);
    ull_t ub = *reinterpret_cast<ull_t*>(&b);
    ull_t uc = *reinterpret_cast<ull_t*>(&c);
    ull_t ud;
    asm("fma.rn.f32x2 %0, %1, %2, %3;" : "=l"(ud) : "l"(ua), "l"(ub), "l"(uc));
    return *reinterpret_cast<float2*>(&ud);
}
__device__ __forceinline__ float2 fmul2_(float2 a, float2 b) {
    ull_t ua = *reinterpret_cast<ull_t*>(&a);
    ull_t ub = *reinterpret_cast<ull_t*>(&b);
    ull_t ud;
    asm("mul.rn.f32x2 %0, %1, %2;" : "=l"(ud) : "l"(ua), "l"(ub));
    return *reinterpret_cast<float2*>(&ud);
}

// scratch (__device__ globals: no allocation APIs allowed)
__device__ float g_Qs[B_*T_*C_];
__device__ float g_Ks[B_*T_*C_];
__device__ float g_V [B_*T_*C_];
__device__ float g_qk[B_*T_];
__device__ float g_sQ[T_];
__device__ float g_sK[T_];
__device__ float g_SR[NCHUNK];

// gammas = linspace(0.96, 0.99, T); r = chunk-local cumulative product
__global__ void scales_kernel() {
    int ch = threadIdx.x;
    if (ch >= NCHUNK) return;
    const float step = 0.03f / 4095.0f;
    float r = 1.0f;
    for (int i = 0; i < CHUNK; ++i) {
        int t = ch * CHUNK + i;
        float g = 0.96f + step * (float)t;
        r *= g;
        g_sQ[t] = r;
        g_sK[t] = 1.0f / r;
    }
    g_SR[ch] = r;
}

// fused QKV projection: out[m,n] = (X[m,:]@W[:,n] + b[n]) * rowscale
#define BM 128
#define BN 64
#define BK 16
__global__ __launch_bounds__(256, 2) void proj_kernel(
        const float* __restrict__ X,
        const float* __restrict__ WQ, const float* __restrict__ bQ,
        const float* __restrict__ WK, const float* __restrict__ bK,
        const float* __restrict__ WV, const float* __restrict__ bV) {
    __shared__ __align__(16) float  As[2][BK][BM];
    __shared__ __align__(16) float2 Bs[2][BK][BN];
    const int tid = threadIdx.x;
    const int which = blockIdx.x >> 3;
    const int n0 = (blockIdx.x & 7) * BN;
    const int m0 = blockIdx.y * BM;
    const float* W    = (which == 0) ? WQ : ((which == 1) ? WK : WV);
    const float* bias = (which == 0) ? bQ : ((which == 1) ? bK : bV);
    float* out        = (which == 0) ? g_Qs : ((which == 1) ? g_Ks : g_V);
    const int tx = tid & 15, ty = tid >> 4;

    float2 acc[4][4];
    #pragma unroll
    for (int i = 0; i < 4; ++i)
        #pragma unroll
        for (int j = 0; j < 4; ++j) acc[i][j] = make_float2(0.f, 0.f);

    {   // stage k-tile 0
        #pragma unroll
        for (int i = 0; i < 2; ++i) {
            int lin = tid + i * 256, m = lin >> 2, k4 = lin & 3;
            float4 v = *(const float4*)&X[(size_t)(m0 + m) * C_ + k4 * 4];
            As[0][k4*4+0][m] = v.x; As[0][k4*4+1][m] = v.y;
            As[0][k4*4+2][m] = v.z; As[0][k4*4+3][m] = v.w;
        }
        int k = tid >> 4, n4 = tid & 15;
        float4 v = *(const float4*)&W[(size_t)k * C_ + n0 + n4 * 4];
        Bs[0][k][n4*4+0] = make_float2(v.x, v.x);
        Bs[0][k][n4*4+1] = make_float2(v.y, v.y);
        Bs[0][k][n4*4+2] = make_float2(v.z, v.z);
        Bs[0][k][n4*4+3] = make_float2(v.w, v.w);
    }
    __syncthreads();

    int cur = 0;
    const int NT = C_ / BK;
    for (int kt = 0; kt < NT; ++kt) {
        float4 pa[2]; float4 pb;
        const bool pre = (kt + 1 < NT);
        if (pre) {
            int k0 = (kt + 1) * BK;
            #pragma unroll
            for (int i = 0; i < 2; ++i) {
                int lin = tid + i * 256, m = lin >> 2, k4 = lin & 3;
                pa[i] = *(const float4*)&X[(size_t)(m0 + m) * C_ + k0 + k4 * 4];
            }
            int k = tid >> 4, n4 = tid & 15;
            pb = *(const float4*)&W[(size_t)(k0 + k) * C_ + n0 + n4 * 4];
        }
        #pragma unroll
        for (int kk = 0; kk < BK; ++kk) {
            float4 a0 = *(const float4*)&As[cur][kk][ty * 8];
            float4 a1 = *(const float4*)&As[cur][kk][ty * 8 + 4];
            float2 a2[4] = { make_float2(a0.x, a0.y), make_float2(a0.z, a0.w),
                             make_float2(a1.x, a1.y), make_float2(a1.z, a1.w) };
            const float4* bp = (const float4*)&Bs[cur][kk][tx * 4];
            float4 bb0 = bp[0], bb1 = bp[1];
            float2 b2[4] = { make_float2(bb0.x, bb0.y), make_float2(bb0.z, bb0.w),
                             make_float2(bb1.x, bb1.y), make_float2(bb1.z, bb1.w) };
            #pragma unroll
            for (int m2 = 0; m2 < 4; ++m2)
                #pragma unroll
                for (int j = 0; j < 4; ++j)
                    acc[m2][j] = ffma2(a2[m2], b2[j], acc[m2][j]);
        }
        if (pre) {
            int nxt = cur ^ 1;
            #pragma unroll
            for (int i = 0; i < 2; ++i) {
                int lin = tid + i * 256, m = lin >> 2, k4 = lin & 3;
                As[nxt][k4*4+0][m] = pa[i].x; As[nxt][k4*4+1][m] = pa[i].y;
                As[nxt][k4*4+2][m] = pa[i].z; As[nxt][k4*4+3][m] = pa[i].w;
            }
            int k = tid >> 4, n4 = tid & 15;
            Bs[nxt][k][n4*4+0] = make_float2(pb.x, pb.x);
            Bs[nxt][k][n4*4+1] = make_float2(pb.y, pb.y);
            Bs[nxt][k][n4*4+2] = make_float2(pb.z, pb.z);
            Bs[nxt][k][n4*4+3] = make_float2(pb.w, pb.w);
            __syncthreads();
            cur = nxt;
        }
    }

    float4 bias4 = *(const float4*)&bias[n0 + tx * 4];
    #pragma unroll
    for (int m2 = 0; m2 < 4; ++m2) {
        #pragma unroll
        for (int h = 0; h < 2; ++h) {
            int m = m0 + ty * 8 + m2 * 2 + h;
            int tt = m & (T_ - 1);
            float s = (which == 0) ? g_sQ[tt] : ((which == 1) ? g_sK[tt] : 1.0f);
            float4 o;
            o.x = ((h ? acc[m2][0].y : acc[m2][0].x) + bias4.x) * s;
            o.y = ((h ? acc[m2][1].y : acc[m2][1].x) + bias4.y) * s;
            o.z = ((h ? acc[m2][2].y : acc[m2][2].x) + bias4.z) * s;
            o.w = ((h ? acc[m2][3].y : acc[m2][3].x) + bias4.w) * s;
            *(float4*)&out[(size_t)m * C_ + n0 + tx * 4] = o;
        }
    }
}

// per-(b,t) dot q~.k~ (== q.k exactly)
__global__ void qk_kernel() {
    int warp = (blockIdx.x * blockDim.x + threadIdx.x) >> 5;
    int lane = threadIdx.x & 31;
    if (warp >= B_ * T_) return;
    const float4* q4 = (const float4*)&g_Qs[(size_t)warp * C_];
    const float4* k4 = (const float4*)&g_Ks[(size_t)warp * C_];
    float2 acc = make_float2(0.f, 0.f);
    #pragma unroll
    for (int i = 0; i < 4; ++i) {
        float4 q = q4[i * 32 + lane];
        float4 k = k4[i * 32 + lane];
        acc = ffma2(make_float2(q.x, q.y), make_float2(k.x, k.y), acc);
        acc = ffma2(make_float2(q.z, q.w), make_float2(k.z, k.w), acc);
    }
    float s = acc.x + acc.y;
    #pragma unroll
    for (int m = 16; m >= 1; m >>= 1) s += __shfl_xor_sync(0xffffffffu, s, m);
    if (lane == 0) g_qk[warp] = s;
}

// scan: 128 CTAs (b, 16-d slab), state in registers, 1 barrier/step
__global__ __launch_bounds__(256, 1) void scan_kernel(
        float* __restrict__ O, float* __restrict__ Sout, int writeS) {
    __shared__ __align__(16) float  sm_q[2][C_];
    __shared__ __align__(16) float  sm_k[2][C_];
    __shared__ __align__(16) float2 sm_vd[3][16];
    __shared__ float sm_qk[3];
    __shared__ __align__(16) float sm_part[2][8][16];
    __shared__ float sm_SR[NCHUNK];

    const int tid = threadIdx.x;
    const int w = tid >> 5, lane = tid & 31;
    const int cz = lane >> 2, dz = lane & 3;
    const int b = blockIdx.x >> 5;
    const int d0 = (blockIdx.x & 31) * 16;
    const int cbase = w * 64 + cz * 8;

    const float* Qb  = g_Qs + (size_t)b * T_ * C_;
    const float* Kb  = g_Ks + (size_t)b * T_ * C_;
    const float* Vb  = g_V  + (size_t)b * T_ * C_;
    const float* qkb = g_qk + (size_t)b * T_;

    float2 S[4][4];
    #pragma unroll
    for (int i = 0; i < 4; ++i)
        #pragma unroll
        for (int j = 0; j < 4; ++j) S[i][j] = make_float2(0.f, 0.f);

    if (tid < NCHUNK) sm_SR[tid] = g_SR[tid];
    {   // stage step 0
        float2 q = *(const float2*)&Qb[2 * tid];
        float2 k = *(const float2*)&Kb[2 * tid];
        *(float2*)&sm_q[0][2 * tid] = q;
        *(float2*)&sm_k[0][2 * tid] = k;
        if (tid < 16) { float v = Vb[d0 + tid]; sm_vd[0][tid] = make_float2(v, v); }
        if (tid == 0) sm_qk[0] = qkb[0];
    }
    __syncthreads();

    for (int t = 0; t < T_; ++t) {
        const int p2 = t & 1;
        const int p3 = t % 3;

        float2 rq, rk; float rv = 0.f, rqk = 0.f;
        const bool pre = (t + 1 < T_);
        if (pre) {
            rq = __ldg((const float2*)&Qb[(size_t)(t + 1) * C_ + 2 * tid]);
            rk = __ldg((const float2*)&Kb[(size_t)(t + 1) * C_ + 2 * tid]);
            if (tid < 16) rv = __ldg(&Vb[(size_t)(t + 1) * C_ + d0 + tid]);
            if (tid == 0) rqk = __ldg(&qkb[t + 1]);
        }

        float4 qa = *(const float4*)&sm_q[p2][cbase];
        float4 qb4 = *(const float4*)&sm_q[p2][cbase + 4];
        float4 ka = *(const float4*)&sm_k[p2][cbase];
        float4 kb4 = *(const float4*)&sm_k[p2][cbase + 4];
        const float4* vp = (const float4*)&sm_vd[p3][dz * 4];
        float4 va = vp[0], vb2 = vp[1];
        float2 q2[4] = { make_float2(qa.x, qa.y), make_float2(qa.z, qa.w),
                         make_float2(qb4.x, qb4.y), make_float2(qb4.z, qb4.w) };
        float2 k2[4] = { make_float2(ka.x, ka.y), make_float2(ka.z, ka.w),
                         make_float2(kb4.x, kb4.y), make_float2(kb4.z, kb4.w) };
        float2 vd2[4] = { make_float2(va.x, va.y), make_float2(va.z, va.w),
                          make_float2(vb2.x, vb2.y), make_float2(vb2.z, vb2.w) };

        // cross partial (uses S BEFORE update)
        float2 acc[4] = { make_float2(0.f,0.f), make_float2(0.f,0.f),
                          make_float2(0.f,0.f), make_float2(0.f,0.f) };
        #pragma unroll
        for (int c2 = 0; c2 < 4; ++c2)
            #pragma unroll
            for (int j = 0; j < 4; ++j)
                acc[j] = ffma2(q2[c2], S[c2][j], acc[j]);
        float cr[4];
        #pragma unroll
        for (int j = 0; j < 4; ++j) cr[j] = acc[j].x + acc[j].y;

        // S += k~ v^T
        #pragma unroll
        for (int c2 = 0; c2 < 4; ++c2)
            #pragma unroll
            for (int j = 0; j < 4; ++j)
                S[c2][j] = ffma2(k2[c2], vd2[j], S[c2][j]);

        #pragma unroll
        for (int j = 0; j < 4; ++j) {
            cr[j] += __shfl_xor_sync(0xffffffffu, cr[j], 4);
            cr[j] += __shfl_xor_sync(0xffffffffu, cr[j], 8);
            cr[j] += __shfl_xor_sync(0xffffffffu, cr[j], 16);
        }
        if (lane < 4)
            *(float4*)&sm_part[p2][w][dz * 4] = make_float4(cr[0], cr[1], cr[2], cr[3]);

        // output for step t-1 (off critical path, warp 0)
        if (t > 0 && w == 0 && lane < 16) {
            const int po = 1 - p2;
            const int pm3 = (t + 2) % 3;    // == (t-1) % 3
            float s = 0.f;
            #pragma unroll
            for (int ww = 0; ww < 8; ++ww) s += sm_part[po][ww][lane];
            float pre_act = s + sm_qk[pm3] * sm_vd[pm3][lane].x;
            O[((size_t)b * T_ + (t - 1)) * C_ + d0 + lane] = tanhf(pre_act);
        }

        if (pre) {
            *(float2*)&sm_q[1 - p2][2 * tid] = rq;
            *(float2*)&sm_k[1 - p2][2 * tid] = rk;
            const int pn3 = (t + 1) % 3;
            if (tid < 16) sm_vd[pn3][tid] = make_float2(rv, rv);
            if (tid == 0) sm_qk[pn3] = rqk;
        }

        if (((t + 1) & (CHUNK - 1)) == 0) {
            float r = sm_SR[t >> 6];
            float2 r2 = make_float2(r, r);
            #pragma unroll
            for (int c2 = 0; c2 < 4; ++c2)
                #pragma unroll
                for (int j = 0; j < 4; ++j)
                    S[c2][j] = fmul2_(S[c2][j], r2);
        }
        __syncthreads();
    }

    // output for t = T-1
    if (w == 0 && lane < 16) {
        const int po = (T_ - 1) & 1;
        const int pm3 = (T_ - 1) % 3;
        float s = 0.f;
        #pragma unroll
        for (int ww = 0; ww < 8; ++ww) s += sm_part[po][ww][lane];
        float pre_act = s + sm_qk[pm3] * sm_vd[pm3][lane].x;
        O[((size_t)b * T_ + (T_ - 1)) * C_ + d0 + lane] = tanhf(pre_act);
    }

    // S_final (already rescaled at the final chunk boundary)
    if (writeS) {
        #pragma unroll
        for (int c2 = 0; c2 < 4; ++c2) {
            int c = cbase + c2 * 2;
            #pragma unroll
            for (int j = 0; j < 4; ++j) {
                int d = d0 + dz * 4 + j;
                Sout[((size_t)b * C_ + c)     * C_ + d] = S[c2][j].x;
                Sout[((size_t)b * C_ + c + 1) * C_ + d] = S[c2][j].y;
            }
        }
    }
}

extern "C" void kernel_launch(void* const* d_in, const int* in_sizes, int n_in,
                              void* d_out, int out_size) {
    const float* X  = (const float*)d_in[0];
    // d_in[1] = S_n (ignored; reference resets state to zero)
    const float* WQ = (const float*)d_in[2];
    const float* bQ = (const float*)d_in[3];
    const float* WK = (const float*)d_in[4];
    const float* bK = (const float*)d_in[5];
    const float* WV = (const float*)d_in[6];
    const float* bV = (const float*)d_in[7];
    float* out = (float*)d_out;

    const int oElems = B_ * T_ * C_;
    const int sElems = B_ * C_ * C_;
    int writeS = (out_size >= oElems + sElems) ? 1 : 0;
    float* Sout = out + oElems;

    scales_kernel<<<1, NCHUNK>>>();
    dim3 pg(24, (B_ * T_) / BM);
    proj_kernel<<<pg, 256>>>(X, WQ, bQ, WK, bK, WV, bV);
    qk_kernel<<<(B_ * T_ * 32) / 256, 256>>>();
    scan_kernel<<<B_ * (C_ / 16), 256>>>(out, Sout, writeS);
}

// round 3
// speedup vs baseline: 1.2239x; 1.2239x over previous
#include <cuda_runtime.h>
#include <cstddef>

#define B_ 4
#define T_ 4096
#define C_ 512
#define CHUNK 64
#define NCHUNK (T_/CHUNK)

typedef unsigned long long ull_t;

__device__ __forceinline__ float2 ffma2(float2 a, float2 b, float2 c) {
    ull_t ua = *reinterpret_cast<ull_t*>(&a);
    ull_t ub = *reinterpret_cast<ull_t*>(&b);
    ull_t uc = *reinterpret_cast<ull_t*>(&c);
    ull_t ud;
    asm("fma.rn.f32x2 %0, %1, %2, %3;" : "=l"(ud) : "l"(ua), "l"(ub), "l"(uc));
    return *reinterpret_cast<float2*>(&ud);
}
__device__ __forceinline__ float2 fmul2_(float2 a, float2 b) {
    ull_t ua = *reinterpret_cast<ull_t*>(&a);
    ull_t ub = *reinterpret_cast<ull_t*>(&b);
    ull_t ud;
    asm("mul.rn.f32x2 %0, %1, %2;" : "=l"(ud) : "l"(ua), "l"(ub));
    return *reinterpret_cast<float2*>(&ud);
}

// scratch (__device__ globals: no allocation APIs allowed)
__device__ float g_Qs[B_*T_*C_];   // Q~ = Q * r_t (chunk-local cumulative gamma)
__device__ float g_Ks[B_*T_*C_];   // K~ = K / r_t
__device__ float g_V [B_*T_*C_];
__device__ float g_OL[B_*T_*C_];   // per-chunk masked local attention output
__device__ float g_sQ[T_];
__device__ float g_sK[T_];
__device__ float g_SR[NCHUNK];

// gammas = linspace(0.96, 0.99, T); r = chunk-local cumulative product
__global__ void scales_kernel() {
    int ch = threadIdx.x;
    if (ch >= NCHUNK) return;
    const float step = 0.03f / 4095.0f;
    float r = 1.0f;
    for (int i = 0; i < CHUNK; ++i) {
        int t = ch * CHUNK + i;
        float g = 0.96f + step * (float)t;
        r *= g;
        g_sQ[t] = r;
        g_sK[t] = 1.0f / r;
    }
    g_SR[ch] = r;
}

// ---------------- fused QKV projection (unchanged from passing R2) ----------------
#define BM 128
#define BN 64
#define BK 16
__global__ __launch_bounds__(256, 2) void proj_kernel(
        const float* __restrict__ X,
        const float* __restrict__ WQ, const float* __restrict__ bQ,
        const float* __restrict__ WK, const float* __restrict__ bK,
        const float* __restrict__ WV, const float* __restrict__ bV) {
    __shared__ __align__(16) float  As[2][BK][BM];
    __shared__ __align__(16) float2 Bs[2][BK][BN];
    const int tid = threadIdx.x;
    const int which = blockIdx.x >> 3;
    const int n0 = (blockIdx.x & 7) * BN;
    const int m0 = blockIdx.y * BM;
    const float* W    = (which == 0) ? WQ : ((which == 1) ? WK : WV);
    const float* bias = (which == 0) ? bQ : ((which == 1) ? bK : bV);
    float* out        = (which == 0) ? g_Qs : ((which == 1) ? g_Ks : g_V);
    const int tx = tid & 15, ty = tid >> 4;

    float2 acc[4][4];
    #pragma unroll
    for (int i = 0; i < 4; ++i)
        #pragma unroll
        for (int j = 0; j < 4; ++j) acc[i][j] = make_float2(0.f, 0.f);

    {
        #pragma unroll
        for (int i = 0; i < 2; ++i) {
            int lin = tid + i * 256, m = lin >> 2, k4 = lin & 3;
            float4 v = *(const float4*)&X[(size_t)(m0 + m) * C_ + k4 * 4];
            As[0][k4*4+0][m] = v.x; As[0][k4*4+1][m] = v.y;
            As[0][k4*4+2][m] = v.z; As[0][k4*4+3][m] = v.w;
        }
        int k = tid >> 4, n4 = tid & 15;
        float4 v = *(const float4*)&W[(size_t)k * C_ + n0 + n4 * 4];
        Bs[0][k][n4*4+0] = make_float2(v.x, v.x);
        Bs[0][k][n4*4+1] = make_float2(v.y, v.y);
        Bs[0][k][n4*4+2] = make_float2(v.z, v.z);
        Bs[0][k][n4*4+3] = make_float2(v.w, v.w);
    }
    __syncthreads();

    int cur = 0;
    const int NT = C_ / BK;
    for (int kt = 0; kt < NT; ++kt) {
        float4 pa[2]; float4 pb;
        const bool pre = (kt + 1 < NT);
        if (pre) {
            int k0 = (kt + 1) * BK;
            #pragma unroll
            for (int i = 0; i < 2; ++i) {
                int lin = tid + i * 256, m = lin >> 2, k4 = lin & 3;
                pa[i] = *(const float4*)&X[(size_t)(m0 + m) * C_ + k0 + k4 * 4];
            }
            int k = tid >> 4, n4 = tid & 15;
            pb = *(const float4*)&W[(size_t)(k0 + k) * C_ + n0 + n4 * 4];
        }
        #pragma unroll
        for (int kk = 0; kk < BK; ++kk) {
            float4 a0 = *(const float4*)&As[cur][kk][ty * 8];
            float4 a1 = *(const float4*)&As[cur][kk][ty * 8 + 4];
            float2 a2[4] = { make_float2(a0.x, a0.y), make_float2(a0.z, a0.w),
                             make_float2(a1.x, a1.y), make_float2(a1.z, a1.w) };
            const float4* bp = (const float4*)&Bs[cur][kk][tx * 4];
            float4 bb0 = bp[0], bb1 = bp[1];
            float2 b2[4] = { make_float2(bb0.x, bb0.y), make_float2(bb0.z, bb0.w),
                             make_float2(bb1.x, bb1.y), make_float2(bb1.z, bb1.w) };
            #pragma unroll
            for (int m2 = 0; m2 < 4; ++m2)
                #pragma unroll
                for (int j = 0; j < 4; ++j)
                    acc[m2][j] = ffma2(a2[m2], b2[j], acc[m2][j]);
        }
        if (pre) {
            int nxt = cur ^ 1;
            #pragma unroll
            for (int i = 0; i < 2; ++i) {
                int lin = tid + i * 256, m = lin >> 2, k4 = lin & 3;
                As[nxt][k4*4+0][m] = pa[i].x; As[nxt][k4*4+1][m] = pa[i].y;
                As[nxt][k4*4+2][m] = pa[i].z; As[nxt][k4*4+3][m] = pa[i].w;
            }
            int k = tid >> 4, n4 = tid & 15;
            Bs[nxt][k][n4*4+0] = make_float2(pb.x, pb.x);
            Bs[nxt][k][n4*4+1] = make_float2(pb.y, pb.y);
            Bs[nxt][k][n4*4+2] = make_float2(pb.z, pb.z);
            Bs[nxt][k][n4*4+3] = make_float2(pb.w, pb.w);
            __syncthreads();
            cur = nxt;
        }
    }

    float4 bias4 = *(const float4*)&bias[n0 + tx * 4];
    #pragma unroll
    for (int m2 = 0; m2 < 4; ++m2) {
        #pragma unroll
        for (int h = 0; h < 2; ++h) {
            int m = m0 + ty * 8 + m2 * 2 + h;
            int tt = m & (T_ - 1);
            float s = (which == 0) ? g_sQ[tt] : ((which == 1) ? g_sK[tt] : 1.0f);
            float4 o;
            o.x = ((h ? acc[m2][0].y : acc[m2][0].x) + bias4.x) * s;
            o.y = ((h ? acc[m2][1].y : acc[m2][1].x) + bias4.y) * s;
            o.z = ((h ? acc[m2][2].y : acc[m2][2].x) + bias4.z) * s;
            o.w = ((h ? acc[m2][3].y : acc[m2][3].x) + bias4.w) * s;
            *(float4*)&out[(size_t)m * C_ + n0 + tx * 4] = o;
        }
    }
}

// ---------------- local (in-chunk) masked attention: O_local = mask(Q~K~^T) V ----------------
// grid = B * NCHUNK = 256 CTAs, 256 threads
#define QS_STRIDE 68
__global__ __launch_bounds__(256) void local_kernel() {
    extern __shared__ float sm3[];
    float* qs = sm3;                              // [64][68]
    float* ks = sm3 + 64 * QS_STRIDE;             // [64][68]
    float* As = sm3 + 2 * 64 * QS_STRIDE;         // [64][64]
    float* vs = As + 64 * 64;                     // [64][128]

    const int tid = threadIdx.x;
    const int b  = blockIdx.x >> 6;
    const int ch = blockIdx.x & 63;
    const int tt = tid >> 4, ss = tid & 15;
    const int r = tid >> 2, cseg = tid & 3;
    const size_t rowbase = (size_t)b * T_ + (size_t)ch * CHUNK;
    const float* Qb = g_Qs + rowbase * C_;
    const float* Kb = g_Ks + rowbase * C_;
    const float* Vb = g_V  + rowbase * C_;

    float2 accA[4][4];
    #pragma unroll
    for (int i = 0; i < 4; ++i)
        #pragma unroll
        for (int j = 0; j < 4; ++j) accA[i][j] = make_float2(0.f, 0.f);

    // Phase A: A = Q~ K~^T over c in 8 tiles of 64
    for (int ct = 0; ct < 8; ++ct) {
        #pragma unroll
        for (int u = 0; u < 4; ++u) {
            float4 qv = *(const float4*)&Qb[(size_t)r * C_ + ct * 64 + cseg * 16 + u * 4];
            float4 kv = *(const float4*)&Kb[(size_t)r * C_ + ct * 64 + cseg * 16 + u * 4];
            *(float4*)&qs[r * QS_STRIDE + cseg * 16 + u * 4] = qv;
            *(float4*)&ks[r * QS_STRIDE + cseg * 16 + u * 4] = kv;
        }
        __syncthreads();
        #pragma unroll 4
        for (int c4 = 0; c4 < 16; ++c4) {
            float4 q[4], k[4];
            #pragma unroll
            for (int i = 0; i < 4; ++i)
                q[i] = *(const float4*)&qs[(tt * 4 + i) * QS_STRIDE + c4 * 4];
            #pragma unroll
            for (int j = 0; j < 4; ++j)
                k[j] = *(const float4*)&ks[(ss * 4 + j) * QS_STRIDE + c4 * 4];
            #pragma unroll
            for (int i = 0; i < 4; ++i)
                #pragma unroll
                for (int j = 0; j < 4; ++j) {
                    accA[i][j] = ffma2(make_float2(q[i].x, q[i].y),
                                       make_float2(k[j].x, k[j].y), accA[i][j]);
                    accA[i][j] = ffma2(make_float2(q[i].z, q[i].w),
                                       make_float2(k[j].z, k[j].w), accA[i][j]);
                }
        }
        __syncthreads();
    }
    // masked write of A (s <= t kept, incl. diagonal = inner term)
    #pragma unroll
    for (int i = 0; i < 4; ++i)
        #pragma unroll
        for (int j = 0; j < 4; ++j) {
            int t = tt * 4 + i, s = ss * 4 + j;
            As[t * 64 + s] = (s <= t) ? (accA[i][j].x + accA[i][j].y) : 0.f;
        }
    __syncthreads();

    // Phase B: O_local = A V, d in 4 tiles of 128
    const int dd = tid & 15;
    const int smax = tt * 4 + 4;
    for (int dt = 0; dt < 4; ++dt) {
        #pragma unroll
        for (int u = 0; u < 8; ++u) {
            float4 vv = *(const float4*)&Vb[(size_t)r * C_ + dt * 128 + cseg * 32 + u * 4];
            *(float4*)&vs[r * 128 + cseg * 32 + u * 4] = vv;
        }
        __syncthreads();
        float2 accO[4][4];
        #pragma unroll
        for (int i = 0; i < 4; ++i)
            #pragma unroll
            for (int p = 0; p < 4; ++p) accO[i][p] = make_float2(0.f, 0.f);
        for (int s = 0; s < smax; ++s) {
            float4 v0 = *(const float4*)&vs[s * 128 + dd * 8];
            float4 v1 = *(const float4*)&vs[s * 128 + dd * 8 + 4];
            float2 vp[4] = { make_float2(v0.x, v0.y), make_float2(v0.z, v0.w),
                             make_float2(v1.x, v1.y), make_float2(v1.z, v1.w) };
            #pragma unroll
            for (int i = 0; i < 4; ++i) {
                float a = As[(tt * 4 + i) * 64 + s];
                float2 a2 = make_float2(a, a);
                #pragma unroll
                for (int p = 0; p < 4; ++p)
                    accO[i][p] = ffma2(a2, vp[p], accO[i][p]);
            }
        }
        #pragma unroll
        for (int i = 0; i < 4; ++i) {
            float4 o0 = make_float4(accO[i][0].x, accO[i][0].y, accO[i][1].x, accO[i][1].y);
            float4 o1 = make_float4(accO[i][2].x, accO[i][2].y, accO[i][3].x, accO[i][3].y);
            float* dst = &g_OL[(rowbase + tt * 4 + i) * C_ + dt * 128 + dd * 8];
            *(float4*)dst = o0;
            *(float4*)(dst + 4) = o1;
        }
        __syncthreads();
    }
}

// ---------------- chunked state scan ----------------
// grid = B * 32 (16-wide d slab), 256 threads; S_T[16][516] in smem; 64 sequential chunks
#define ST_STRIDE 516
#define QK_STRIDE 132
__global__ __launch_bounds__(256) void scan2_kernel(
        float* __restrict__ O, float* __restrict__ Sout, int writeS) {
    extern __shared__ float sm4[];
    float* ST = sm4;                        // [16][516]
    float* QK = sm4 + 16 * ST_STRIDE;       // [64][132]
    float* VS = QK + 64 * QK_STRIDE;        // [64][16]

    const int tid = threadIdx.x;
    const int b  = blockIdx.x >> 5;
    const int d0 = (blockIdx.x & 31) * 16;
    const int tt = tid >> 4, dd = tid & 15;  // GEMM1: t-group/d; GEMM2: c-group/d
    const int r = tid >> 2, cseg = tid & 3;
    const float* Qb  = g_Qs + (size_t)b * T_ * C_;
    const float* Kb  = g_Ks + (size_t)b * T_ * C_;
    const float* Vb  = g_V  + (size_t)b * T_ * C_;
    const float* OLb = g_OL + (size_t)b * T_ * C_;
    float* Ob = O + (size_t)b * T_ * C_;

    for (int i = tid; i < 16 * ST_STRIDE; i += 256) ST[i] = 0.f;

    float4 P[8]; float4 Pv; float Pol[4];
    {   // prologue: prefetch chunk 0, q tile 0 + v slab + O_local
        #pragma unroll
        for (int u = 0; u < 8; ++u)
            P[u] = __ldg((const float4*)&Qb[(size_t)r * C_ + cseg * 32 + u * 4]);
        Pv = __ldg((const float4*)&Vb[(size_t)r * C_ + d0 + cseg * 4]);
        #pragma unroll
        for (int i = 0; i < 4; ++i)
            Pol[i] = __ldg(&OLb[(size_t)(tt * 4 + i) * C_ + d0 + dd]);
    }

    float2 accC[4];
    #pragma unroll
    for (int i = 0; i < 4; ++i) accC[i] = make_float2(0.f, 0.f);

    for (int ch = 0; ch < NCHUNK; ++ch) {
        const size_t crow = (size_t)ch * CHUNK;
        for (int ph = 0; ph < 8; ++ph) {
            __syncthreads();
            #pragma unroll
            for (int u = 0; u < 8; ++u)
                *(float4*)&QK[r * QK_STRIDE + cseg * 32 + u * 4] = P[u];
            if (ph == 0)
                *(float4*)&VS[r * 16 + cseg * 4] = Pv;
            __syncthreads();

            // prefetch next tile (latency hidden behind compute)
            {
                const float* src; size_t rb; int ctb;
                if (ph < 3)       { src = Qb; rb = crow; ctb = ph + 1; }
                else if (ph == 3) { src = Kb; rb = crow; ctb = 0; }
                else if (ph < 7)  { src = Kb; rb = crow; ctb = ph - 3; }
                else {
                    int chn = (ch < NCHUNK - 1) ? ch + 1 : ch;
                    rb = (size_t)chn * CHUNK; src = Qb; ctb = 0;
                    Pv = __ldg((const float4*)&Vb[(rb + r) * C_ + d0 + cseg * 4]);
                    #pragma unroll
                    for (int i = 0; i < 4; ++i)
                        Pol[i] = __ldg(&OLb[(rb + tt * 4 + i) * C_ + d0 + dd]);
                }
                #pragma unroll
                for (int u = 0; u < 8; ++u)
                    P[u] = __ldg((const float4*)&src[(rb + r) * C_ + ctb * 128 + cseg * 32 + u * 4]);
            }

            if (ph < 4) {
                // GEMM1: accC[t] += sum_c q~[t][c] * S[c][d]
                const int cb = ph * 128;
                #pragma unroll 4
                for (int c4 = 0; c4 < 32; ++c4) {
                    float4 sv = *(const float4*)&ST[dd * ST_STRIDE + cb + c4 * 4];
                    float2 s01 = make_float2(sv.x, sv.y), s23 = make_float2(sv.z, sv.w);
                    #pragma unroll
                    for (int i = 0; i < 4; ++i) {
                        float4 qv = *(const float4*)&QK[(tt * 4 + i) * QK_STRIDE + c4 * 4];
                        accC[i] = ffma2(make_float2(qv.x, qv.y), s01, accC[i]);
                        accC[i] = ffma2(make_float2(qv.z, qv.w), s23, accC[i]);
                    }
                }
                if (ph == 3) {
                    #pragma unroll
                    for (int i = 0; i < 4; ++i) {
                        float o = accC[i].x + accC[i].y + Pol[i];
                        Ob[(crow + tt * 4 + i) * C_ + d0 + dd] = tanhf(o);
                        accC[i] = make_float2(0.f, 0.f);
                    }
                }
            } else {
                // GEMM2: S[c][d] = (S[c][d] + sum_s k~[s][c] v[s][d]) * R
                const int c0 = (ph - 4) * 128 + tt * 8;
                float4 s0 = *(const float4*)&ST[dd * ST_STRIDE + c0];
                float4 s1 = *(const float4*)&ST[dd * ST_STRIDE + c0 + 4];
                float2 a0 = make_float2(s0.x, s0.y), a1 = make_float2(s0.z, s0.w);
                float2 a2 = make_float2(s1.x, s1.y), a3 = make_float2(s1.z, s1.w);
                #pragma unroll 8
                for (int s = 0; s < CHUNK; ++s) {
                    float vv = VS[s * 16 + dd];
                    float2 v2 = make_float2(vv, vv);
                    float4 k0 = *(const float4*)&QK[s * QK_STRIDE + tt * 8];
                    float4 k1 = *(const float4*)&QK[s * QK_STRIDE + tt * 8 + 4];
                    a0 = ffma2(make_float2(k0.x, k0.y), v2, a0);
                    a1 = ffma2(make_float2(k0.z, k0.w), v2, a1);
                    a2 = ffma2(make_float2(k1.x, k1.y), v2, a2);
                    a3 = ffma2(make_float2(k1.z, k1.w), v2, a3);
                }
                float R = __ldg(&g_SR[ch]);
                float2 R2 = make_float2(R, R);
                a0 = fmul2_(a0, R2); a1 = fmul2_(a1, R2);
                a2 = fmul2_(a2, R2); a3 = fmul2_(a3, R2);
                *(float4*)&ST[dd * ST_STRIDE + c0]     = make_float4(a0.x, a0.y, a1.x, a1.y);
                *(float4*)&ST[dd * ST_STRIDE + c0 + 4] = make_float4(a2.x, a2.y, a3.x, a3.y);
            }
        }
    }

    __syncthreads();
    if (writeS) {
        for (int idx = tid; idx < C_ * 16; idx += 256) {
            int c = idx >> 4, d = idx & 15;
            Sout[((size_t)b * C_ + c) * C_ + d0 + d] = ST[d * ST_STRIDE + c];
        }
    }
}

extern "C" void kernel_launch(void* const* d_in, const int* in_sizes, int n_in,
                              void* d_out, int out_size) {
    const float* X  = (const float*)d_in[0];
    // d_in[1] = S_n (ignored; reference resets state to zero)
    const float* WQ = (const float*)d_in[2];
    const float* bQ = (const float*)d_in[3];
    const float* WK = (const float*)d_in[4];
    const float* bK = (const float*)d_in[5];
    const float* WV = (const float*)d_in[6];
    const float* bV = (const float*)d_in[7];
    float* out = (float*)d_out;

    const int oElems = B_ * T_ * C_;
    const int sElems = B_ * C_ * C_;
    int writeS = (out_size >= oElems + sElems) ? 1 : 0;
    float* Sout = out + oElems;

    const int sm3 = (2 * 64 * QS_STRIDE + 64 * 64 + 64 * 128) * 4;
    const int sm4 = (16 * ST_STRIDE + 64 * QK_STRIDE + 64 * 16) * 4;
    cudaFuncSetAttribute(local_kernel, cudaFuncAttributeMaxDynamicSharedMemorySize, sm3);
    cudaFuncSetAttribute(scan2_kernel, cudaFuncAttributeMaxDynamicSharedMemorySize, sm4);

    scales_kernel<<<1, NCHUNK>>>();
    dim3 pg(24, (B_ * T_) / BM);
    proj_kernel<<<pg, 256>>>(X, WQ, bQ, WK, bK, WV, bV);
    local_kernel<<<B_ * NCHUNK, 256, sm3>>>();
    scan2_kernel<<<B_ * 32, 256, sm4>>>(out, Sout, writeS);
}